// round 15
// baseline (speedup 1.0000x reference)
#include <cuda_runtime.h>
#include <cuda_fp16.h>
#include <math.h>
#include <stdint.h>

// ---------------------------------------------------------------------------
// ChannelCrossAttention — HMMA fp16 1-term. GEMMs: 128x128 CTA tile (warp
// 64x64, 4 warps), 3 CTAs/SM (12 warps) for latency hiding under the 170-reg
// cap. Token-major q/k/v scratch; gram via ldmatrix.trans; warp softmax.
// ---------------------------------------------------------------------------

// packed 2xfp16 per u32
__device__ uint32_t g_x_h[2u * 32768u * 256u];     // [s][m][kpair]
__device__ uint32_t g_wq_h[2u * 1536u * 256u];     // [s][c][kpair]
__device__ uint32_t g_wp_h[2u * 512u * 256u];
// q/k/v token-major: [s][w 0..2][b][n 4096][cpair 256]
__device__ uint32_t g_qkv_h[2u * 3u * 8u * 4096u * 256u];
// attention out token-major: [s][b][n][kpair 256]
__device__ uint32_t g_att_h[2u * 8u * 4096u * 256u];
// per-channel sumsq partials: [s][w(q/k)][b][c 512][part 64]
__device__ float g_nrm[2u * 2u * 8u * 512u * 64u];
// Gram partials [g 128][chunk 8][64*64]
__device__ float g_pgram[128u * 8u * 4096u];
// P packed fp16 [g][d 64][epair 32]
__device__ uint32_t g_p_h[128u * 2048u];

// ---------------------------------------------------------------------------
__device__ __forceinline__ uint32_t smem_u32(const void* p) {
    uint32_t a;
    asm("{ .reg .u64 t; cvta.to.shared.u64 t, %1; cvt.u32.u64 %0, t; }" : "=r"(a) : "l"(p));
    return a;
}
__device__ __forceinline__ uint32_t swz(uint32_t off) { return off ^ (((off) >> 3) & 0x70); }

__device__ __forceinline__ void ldmx4(uint32_t& r0, uint32_t& r1, uint32_t& r2, uint32_t& r3,
                                      uint32_t addr) {
    asm volatile("ldmatrix.sync.aligned.m8n8.x4.shared.b16 {%0,%1,%2,%3}, [%4];"
        : "=r"(r0), "=r"(r1), "=r"(r2), "=r"(r3) : "r"(addr));
}
__device__ __forceinline__ void ldmx4t(uint32_t& r0, uint32_t& r1, uint32_t& r2, uint32_t& r3,
                                       uint32_t addr) {
    asm volatile("ldmatrix.sync.aligned.m8n8.x4.trans.shared.b16 {%0,%1,%2,%3}, [%4];"
        : "=r"(r0), "=r"(r1), "=r"(r2), "=r"(r3) : "r"(addr));
}
__device__ __forceinline__ void mma_h(float* c, const uint32_t* a, const uint32_t* b) {
    asm volatile("mma.sync.aligned.m16n8k16.row.col.f32.f16.f16.f32 "
        "{%0,%1,%2,%3}, {%4,%5,%6,%7}, {%8,%9}, {%0,%1,%2,%3};"
        : "+f"(c[0]), "+f"(c[1]), "+f"(c[2]), "+f"(c[3])
        : "r"(a[0]), "r"(a[1]), "r"(a[2]), "r"(a[3]), "r"(b[0]), "r"(b[1]));
}
#define CP_ASYNC16(dst, src) \
    asm volatile("cp.async.cg.shared.global [%0], [%1], 16;" :: "r"(dst), "l"(src))
#define CP_COMMIT() asm volatile("cp.async.commit_group;")
#define CP_WAIT0()  asm volatile("cp.async.wait_group 0;")
#define CP_WAIT1()  asm volatile("cp.async.wait_group 1;")

__device__ __forceinline__ uint32_t packh(__half a, __half b) {
    return (uint32_t)__half_as_ushort(a) | ((uint32_t)__half_as_ushort(b) << 16);
}
__device__ __forceinline__ uint32_t cvt1h(float a, float b) {
    return packh(__float2half_rn(a), __float2half_rn(b));
}

// GEMM smem: stage = A 16K | B 16K = 32KB, 2 stages (epilogue reuses base)
#define SQ_A(st) ((st) * 32768 + 0)
#define SQ_B(st) ((st) * 32768 + 16384)
#define GEMM_SMEM (65536 + 1024)
// gram smem: stage = q 8K | k 8K = 16KB, 2 stages
#define SG_Q(st) ((st) * 16384 + 0)
#define SG_K(st) ((st) * 16384 + 8192)
#define GRAM_SMEM (32768 + 1024)
// pv smem: v 16K | P 8K
#define SP_V 0
#define SP_P 16384
#define PV_SMEM (24576 + 1024)

// ---------------------------------------------------------------------------
// Prep kernels
// ---------------------------------------------------------------------------
__global__ __launch_bounds__(256) void prep_x_kernel(
    const float* __restrict__ x, const float* __restrict__ x_d)
{
    int idx = blockIdx.x * 256 + threadIdx.x;
    int s = idx >> 23;
    int r = idx & 0x7FFFFF;
    int m = r >> 8, kp = r & 255;
    const float* X = s ? x_d : x;
    float2 v = *(const float2*)&X[(size_t)m * 512 + kp * 2];
    g_x_h[idx] = cvt1h(v.x, v.y);
}

__global__ __launch_bounds__(256) void prep_w_kernel(
    const float* __restrict__ Wq_r, const float* __restrict__ Wq_T,
    const float* __restrict__ Wp_r, const float* __restrict__ Wp_T)
{
    int idx = blockIdx.x * 256 + threadIdx.x;
    const int TQ = 2 * 1536 * 256;
    const int TP = 2 * 512 * 256;
    if (idx < TQ) {
        int s = idx / (1536 * 256);
        int r = idx % (1536 * 256);
        int c = r >> 8, kp = r & 255;
        const float* W = s ? Wq_T : Wq_r;
        g_wq_h[idx] = cvt1h(W[(size_t)(2 * kp) * 1536 + c],
                            W[(size_t)(2 * kp + 1) * 1536 + c]);
    } else if (idx < TQ + TP) {
        int i2 = idx - TQ;
        int s = i2 / (512 * 256);
        int r = i2 % (512 * 256);
        int c = r >> 8, kp = r & 255;
        const float* W = s ? Wp_T : Wp_r;
        g_wp_h[i2] = cvt1h(W[(size_t)(2 * kp) * 512 + c],
                           W[(size_t)(2 * kp + 1) * 512 + c]);
    }
}

// ---------------------------------------------------------------------------
// GEMM core: CTA 128(m) x 128(n), 4 warps (wm 2 x wn 2), warp 64x64.
// ---------------------------------------------------------------------------
__device__ __forceinline__ void fill2(uint32_t sb, int st, int tid, int kp0,
    const uint32_t* __restrict__ A, size_t aBase,
    const uint32_t* __restrict__ B, size_t bBase)
{
#pragma unroll
    for (int it = 0; it < 8; it++) {
        int idx = tid + it * 128;          // 1024 lines for A
        int r = idx >> 3, c16 = idx & 7;
        uint32_t dsw = swz((uint32_t)(r * 128 + c16 * 16));
        CP_ASYNC16(sb + SQ_A(st) + dsw, A + aBase + (size_t)r * 256 + kp0 + c16 * 4);
    }
#pragma unroll
    for (int it = 0; it < 8; it++) {
        int idx = tid + it * 128;          // 1024 lines for B
        int r = idx >> 3, c16 = idx & 7;
        uint32_t dsw = swz((uint32_t)(r * 128 + c16 * 16));
        CP_ASYNC16(sb + SQ_B(st) + dsw, B + bBase + (size_t)r * 256 + kp0 + c16 * 4);
    }
    CP_COMMIT();
}

__device__ __forceinline__ void mma_big(uint32_t sb, int st, int wm, int wn, int lane,
                                        float acc[4][8][4])
{
    const int aRow  = wm * 64 + (lane & 15);
    const int aColb = (lane >> 4) * 16;
    const int bRow  = wn * 64 + (lane & 7) + ((lane >> 4) & 1) * 8;
    const int bColb = ((lane >> 3) & 1) * 16;
#pragma unroll
    for (int kk = 0; kk < 4; kk++) {
        uint32_t ah[4][4], bf[8][2];
#pragma unroll
        for (int mt = 0; mt < 4; mt++)
            ldmx4(ah[mt][0], ah[mt][1], ah[mt][2], ah[mt][3],
                  sb + SQ_A(st) + swz((uint32_t)((aRow + mt * 16) * 128 + aColb + kk * 32)));
#pragma unroll
        for (int j = 0; j < 4; j++)
            ldmx4(bf[2 * j][0], bf[2 * j][1], bf[2 * j + 1][0], bf[2 * j + 1][1],
                  sb + SQ_B(st) + swz((uint32_t)((bRow + j * 16) * 128 + bColb + kk * 32)));
#pragma unroll
        for (int mt = 0; mt < 4; mt++)
#pragma unroll
            for (int nj = 0; nj < 8; nj++)
                mma_h(acc[mt][nj], ah[mt], bf[nj]);
    }
}

// ---------------------------------------------------------------------------
// Kernel 1: qkv GEMM.  grid (cTile 12, mTile 256, s 2), 128 threads, 3 CTA/SM.
// ---------------------------------------------------------------------------
__global__ __launch_bounds__(128, 3) void qkv_mma_kernel()
{
    extern __shared__ char dsm[];
    uint32_t sbr = smem_u32(dsm);
    uint32_t sb = (sbr + 1023) & ~1023u;
    char* ab = dsm + (sb - sbr);

    const int tid = threadIdx.x;
    const int wid = tid >> 5;          // 0..3
    const int lane = tid & 31;
    const int wm = wid & 1, wn = wid >> 1;
    const int s = blockIdx.z;
    const int m0 = blockIdx.y * 128;
    const int c0 = blockIdx.x * 128;
    const int b = m0 >> 12, n0 = m0 & 4095;
    const int which = c0 >> 9;          // 0=q 1=k 2=v
    const int cb512 = c0 - which * 512; // 0/128/256/384

    const size_t aBase = ((size_t)s * 32768 + m0) * 256;
    const size_t bBase = ((size_t)s * 1536 + c0) * 256;

    float acc[4][8][4];
#pragma unroll
    for (int i = 0; i < 4; i++)
#pragma unroll
        for (int j = 0; j < 8; j++)
#pragma unroll
            for (int r = 0; r < 4; r++) acc[i][j][r] = 0.f;

    fill2(sb, 0, tid, 0, g_x_h, aBase, g_wq_h, bBase);
    for (int c = 0; c < 8; c++) {
        int st = c & 1;
        if (c < 7) fill2(sb, st ^ 1, tid, (c + 1) * 32, g_x_h, aBase, g_wq_h, bBase);
        if (c < 7) CP_WAIT1(); else CP_WAIT0();
        __syncthreads();
        mma_big(sb, st, wm, wn, lane, acc);
        __syncthreads();
    }

    // epilogue: frags -> sbuf[t 128][cp 64] (pitch 68) + exact norms for q/k
    uint32_t* sbuf = (uint32_t*)ab;
    const size_t rb = ((size_t)((s * 3 + which) * 8 + b)) * 4096;

#pragma unroll
    for (int nj = 0; nj < 8; nj++) {
        float r2a = 0.f, r2b = 0.f;
#pragma unroll
        for (int mt = 0; mt < 4; mt++) {
            int tl = wm * 64 + mt * 16 + (lane >> 2);
            int cpl = wn * 32 + nj * 4 + (lane & 3);    // local cpair 0..63
            sbuf[tl * 68 + cpl]       = cvt1h(acc[mt][nj][0], acc[mt][nj][1]);
            sbuf[(tl + 8) * 68 + cpl] = cvt1h(acc[mt][nj][2], acc[mt][nj][3]);
            if (which < 2) {
                r2a += acc[mt][nj][0] * acc[mt][nj][0] + acc[mt][nj][2] * acc[mt][nj][2];
                r2b += acc[mt][nj][1] * acc[mt][nj][1] + acc[mt][nj][3] * acc[mt][nj][3];
            }
        }
        if (which < 2) {
            r2a += __shfl_xor_sync(0xFFFFFFFFu, r2a, 4);
            r2b += __shfl_xor_sync(0xFFFFFFFFu, r2b, 4);
            r2a += __shfl_xor_sync(0xFFFFFFFFu, r2a, 8);
            r2b += __shfl_xor_sync(0xFFFFFFFFu, r2b, 8);
            r2a += __shfl_xor_sync(0xFFFFFFFFu, r2a, 16);
            r2b += __shfl_xor_sync(0xFFFFFFFFu, r2b, 16);
            if (lane < 4) {
                int cch = cb512 + wn * 64 + nj * 8 + 2 * lane;
                int part = (n0 >> 7) * 2 + wm;
                size_t nb = ((((size_t)(s * 2 + which)) * 8 + b) * 512 + cch) * 64 + part;
                g_nrm[nb]      = r2a;
                g_nrm[nb + 64] = r2b;
            }
        }
    }
    __syncthreads();

    // coalesced copy sbuf -> g_qkv_h (256B per row segment)
    const int cp0 = cb512 >> 1;     // 0/64/128/192
#pragma unroll
    for (int it = 0; it < 16; it++) {
        int idx = tid + it * 128;       // 2048 x 16B chunks
        int row = idx >> 4;
        int q4 = idx & 15;
        uint4 v4 = *(uint4*)&sbuf[row * 68 + q4 * 4];
        *(uint4*)&g_qkv_h[(rb + n0 + row) * 256 + cp0 + q4 * 4] = v4;
    }
}

// ---------------------------------------------------------------------------
// Kernel 2a: Gram partials via ldmatrix.trans. grid (chunk 8, bh 64, s 2)
// ---------------------------------------------------------------------------
__global__ __launch_bounds__(256) void attn_gram_kernel()
{
    extern __shared__ char dsm[];
    uint32_t sbr = smem_u32(dsm);
    uint32_t sb = (sbr + 1023) & ~1023u;

    const int tid = threadIdx.x;
    const int wid = tid >> 5;
    const int lane = tid & 31;
    const int wm = wid & 1, wn = wid >> 1;
    const int chunk = blockIdx.x;
    const int bh = blockIdx.y;
    const int s = blockIdx.z;
    const int b = bh >> 3, h = bh & 7;
    const int so = s ^ 1;
    const int g = s * 64 + bh;

    const size_t qb = ((size_t)((s  * 3 + 0) * 8 + b)) * 4096;
    const size_t kb = ((size_t)((so * 3 + 1) * 8 + b)) * 4096;

    float acc[2][2][4];
#pragma unroll
    for (int i = 0; i < 2; i++)
#pragma unroll
        for (int j = 0; j < 2; j++)
#pragma unroll
            for (int r = 0; r < 4; r++) acc[i][j][r] = 0.f;

    auto fill_sub = [&](int st, int sub) {
        int tok0 = chunk * 512 + sub * 64;
#pragma unroll
        for (int it = 0; it < 2; it++) {
            int idx = tid + it * 256;
            int r = idx >> 3, c16 = idx & 7;
            uint32_t dsw = swz((uint32_t)(r * 128 + c16 * 16));
            CP_ASYNC16(sb + SG_Q(st) + dsw, g_qkv_h + (qb + tok0 + r) * 256 + h * 32 + c16 * 4);
            CP_ASYNC16(sb + SG_K(st) + dsw, g_qkv_h + (kb + tok0 + r) * 256 + h * 32 + c16 * 4);
        }
        CP_COMMIT();
    };

    const int aTrowOff = ((lane >> 4) & 1) * 8 + (lane & 7);
    const int aDcolOff = ((lane >> 3) & 1) * 8;
    const int bTrowOff = ((lane >> 3) & 1) * 8 + (lane & 7);
    const int bEcolOff = ((lane >> 4) & 1) * 8;

    fill_sub(0, 0);
    for (int sub = 0; sub < 8; sub++) {
        int st = sub & 1;
        if (sub < 7) fill_sub(st ^ 1, sub + 1);
        if (sub < 7) CP_WAIT1(); else CP_WAIT0();
        __syncthreads();
#pragma unroll
        for (int kk = 0; kk < 4; kk++) {
            const int t0 = kk * 16;
            uint32_t qh[2][4], kf[2][2];
#pragma unroll
            for (int mt = 0; mt < 2; mt++) {
                int d0 = wm * 32 + mt * 16;
                ldmx4t(qh[mt][0], qh[mt][1], qh[mt][2], qh[mt][3],
                       sb + SG_Q(st) + swz((uint32_t)((t0 + aTrowOff) * 128 + (d0 + aDcolOff) * 2)));
            }
            {
                int e0 = wn * 16;
                ldmx4t(kf[0][0], kf[0][1], kf[1][0], kf[1][1],
                       sb + SG_K(st) + swz((uint32_t)((t0 + bTrowOff) * 128 + (e0 + bEcolOff) * 2)));
            }
#pragma unroll
            for (int mt = 0; mt < 2; mt++)
#pragma unroll
                for (int nt = 0; nt < 2; nt++)
                    mma_h(acc[mt][nt], qh[mt], kf[nt]);
        }
        __syncthreads();
    }

    const size_t base = (size_t)(g * 8 + chunk) * 4096;
#pragma unroll
    for (int mt = 0; mt < 2; mt++)
#pragma unroll
        for (int nt = 0; nt < 2; nt++) {
            int m = wm * 32 + mt * 16 + (lane >> 2);
            int col = wn * 16 + nt * 8 + 2 * (lane & 3);
            *(float2*)&g_pgram[base + m * 64 + col] = make_float2(acc[mt][nt][0], acc[mt][nt][1]);
            *(float2*)&g_pgram[base + (m + 8) * 64 + col] = make_float2(acc[mt][nt][2], acc[mt][nt][3]);
        }
}

// ---------------------------------------------------------------------------
// Kernel 2b: reduce partials + norms, softmax (warp-parallel), emit P fp16
// ---------------------------------------------------------------------------
__global__ __launch_bounds__(256) void attn_softmax_kernel(
    const float* __restrict__ temp_rgb, const float* __restrict__ temp_T)
{
    const int g = blockIdx.x;
    const int s = g >> 6;
    const int bh = g & 63;
    const int b = bh >> 3, h = bh & 7;
    const int so = s ^ 1;
    const float temp = (s ? temp_T : temp_rgb)[h];

    __shared__ float qinv[64], kinv[64];
    const int tid = threadIdx.x;

    if (tid < 64) {
        float sq = 0.f;
        size_t nb = (((size_t)(s * 2 + 0) * 8 + b) * 512 + h * 64 + tid) * 64;
#pragma unroll
        for (int t = 0; t < 64; t++) sq += g_nrm[nb + t];
        qinv[tid] = 1.f / fmaxf(sqrtf(sq), 1e-12f);
    } else if (tid < 128) {
        float sk = 0.f;
        size_t nb = (((size_t)(so * 2 + 1) * 8 + b) * 512 + h * 64 + tid - 64) * 64;
#pragma unroll
        for (int t = 0; t < 64; t++) sk += g_nrm[nb + t];
        kinv[tid - 64] = 1.f / fmaxf(sqrtf(sk), 1e-12f);
    }
    __syncthreads();

    const int wid = tid >> 5, lane = tid & 31;
    const int j0 = lane * 2;
    const float ki0 = kinv[j0], ki1 = kinv[j0 + 1];
#pragma unroll
    for (int r = 0; r < 8; r++) {
        int d = wid * 8 + r;
        float v0 = 0.f, v1 = 0.f;
#pragma unroll
        for (int c = 0; c < 8; c++) {
            float2 pv = *(const float2*)&g_pgram[(size_t)(g * 8 + c) * 4096 + d * 64 + j0];
            v0 += pv.x; v1 += pv.y;
        }
        float sc = temp * qinv[d];
        v0 *= sc * ki0;
        v1 *= sc * ki1;
        float mx = fmaxf(v0, v1);
#pragma unroll
        for (int o = 16; o; o >>= 1) mx = fmaxf(mx, __shfl_xor_sync(0xFFFFFFFFu, mx, o));
        float e0 = __expf(v0 - mx), e1 = __expf(v1 - mx);
        float sm = e0 + e1;
#pragma unroll
        for (int o = 16; o; o >>= 1) sm += __shfl_xor_sync(0xFFFFFFFFu, sm, o);
        float inv = 1.f / sm;
        g_p_h[(size_t)g * 2048 + d * 32 + lane] = cvt1h(e0 * inv, e1 * inv);
    }
}

// ---------------------------------------------------------------------------
// Kernel 2c: out = P @ v. grid (tile 32, bh 64, s 2)
// ---------------------------------------------------------------------------
__global__ __launch_bounds__(256) void attn_pv_kernel()
{
    extern __shared__ char dsm[];
    uint32_t sbr = smem_u32(dsm);
    uint32_t sb = (sbr + 1023) & ~1023u;

    const int tid = threadIdx.x;
    const int wid = tid >> 5;
    const int lane = tid & 31;
    const int wm = wid & 1, wn = wid >> 1;
    const int n0 = blockIdx.x * 128;
    const int bh = blockIdx.y;
    const int s = blockIdx.z;
    const int b = bh >> 3, h = bh & 7;
    const int so = s ^ 1;
    const int g = s * 64 + bh;
    const size_t vb = ((size_t)((so * 3 + 2) * 8 + b)) * 4096;

#pragma unroll
    for (int it = 0; it < 4; it++) {
        int idx = tid + it * 256;
        int r = idx >> 3, c16 = idx & 7;
        uint32_t dsw = swz((uint32_t)(r * 128 + c16 * 16));
        CP_ASYNC16(sb + SP_V + dsw, g_qkv_h + (vb + n0 + r) * 256 + h * 32 + c16 * 4);
    }
#pragma unroll
    for (int it = 0; it < 2; it++) {
        int idx = tid + it * 256;
        int r = idx >> 3, c16 = idx & 7;
        uint32_t dsw = swz((uint32_t)(r * 128 + c16 * 16));
        CP_ASYNC16(sb + SP_P + dsw, g_p_h + (size_t)g * 2048 + r * 32 + c16 * 4);
    }
    CP_COMMIT();
    CP_WAIT0();
    __syncthreads();

    float acc[4][2][4];
#pragma unroll
    for (int i = 0; i < 4; i++)
#pragma unroll
        for (int j = 0; j < 2; j++)
#pragma unroll
            for (int r = 0; r < 4; r++) acc[i][j][r] = 0.f;

    const int aRow  = wm * 64 + (lane & 15);
    const int aColb = (lane >> 4) * 16;
    const int bRow  = wn * 16 + (lane & 7) + ((lane >> 4) & 1) * 8;
    const int bColb = ((lane >> 3) & 1) * 16;

#pragma unroll
    for (int kk = 0; kk < 4; kk++) {
        uint32_t vh[4][4], pf[2][2];
#pragma unroll
        for (int mt = 0; mt < 4; mt++)
            ldmx4(vh[mt][0], vh[mt][1], vh[mt][2], vh[mt][3],
                  sb + SP_V + swz((uint32_t)((aRow + mt * 16) * 128 + aColb + kk * 32)));
        ldmx4(pf[0][0], pf[0][1], pf[1][0], pf[1][1],
              sb + SP_P + swz((uint32_t)(bRow * 128 + bColb + kk * 32)));
#pragma unroll
        for (int mt = 0; mt < 4; mt++)
#pragma unroll
            for (int nt = 0; nt < 2; nt++)
                mma_h(acc[mt][nt], vh[mt], pf[nt]);
    }

    const size_t ob = (size_t)(s * 8 + b) * 4096;
#pragma unroll
    for (int mt = 0; mt < 4; mt++) {
        int t = n0 + wm * 64 + mt * 16 + (lane >> 2);
#pragma unroll
        for (int nt = 0; nt < 2; nt++) {
            int dp = wn * 8 + nt * 4 + (lane & 3);
            size_t a0 = (ob + t) * 256 + h * 32 + dp;
            g_att_h[a0]           = cvt1h(acc[mt][nt][0], acc[mt][nt][1]);
            g_att_h[a0 + 8 * 256] = cvt1h(acc[mt][nt][2], acc[mt][nt][3]);
        }
    }
}

// ---------------------------------------------------------------------------
// Kernel 3: proj GEMM. grid (cTile 4, nTile 32, sb 16), 128 threads, 3 CTA/SM.
// ---------------------------------------------------------------------------
__global__ __launch_bounds__(128, 3) void proj_mma_kernel(
    const float* __restrict__ br, const float* __restrict__ bt,
    float* __restrict__ out)
{
    extern __shared__ char dsm[];
    uint32_t sbr = smem_u32(dsm);
    uint32_t sb = (sbr + 1023) & ~1023u;
    char* ab = dsm + (sb - sbr);

    const int tid = threadIdx.x;
    const int wid = tid >> 5;
    const int lane = tid & 31;
    const int wm = wid & 1, wn = wid >> 1;
    const int z = blockIdx.z;
    const int s = z >> 3, b = z & 7;
    const float* __restrict__ bias = s ? bt : br;
    const int n0 = blockIdx.y * 128;
    const int c0 = blockIdx.x * 128;

    const size_t aBase = (((size_t)(s * 8 + b)) * 4096 + n0) * 256;
    const size_t bBase = ((size_t)s * 512 + c0) * 256;

    float acc[4][8][4];
#pragma unroll
    for (int i = 0; i < 4; i++)
#pragma unroll
        for (int j = 0; j < 8; j++)
#pragma unroll
            for (int r = 0; r < 4; r++) acc[i][j][r] = 0.f;

    fill2(sb, 0, tid, 0, g_att_h, aBase, g_wp_h, bBase);
    for (int c = 0; c < 8; c++) {
        int st = c & 1;
        if (c < 7) fill2(sb, st ^ 1, tid, (c + 1) * 32, g_att_h, aBase, g_wp_h, bBase);
        if (c < 7) CP_WAIT1(); else CP_WAIT0();
        __syncthreads();
        mma_big(sb, st, wm, wn, lane, acc);
        __syncthreads();
    }

    // epilogue: [token][channel] + bias via smem transpose (2 passes over wm)
    float* sT = (float*)ab;   // 64 x 132 fp32
    float* outp = out + (size_t)(s * 8 + b) * 2097152;
#pragma unroll
    for (int p = 0; p < 2; p++) {
        if (wm == p) {
#pragma unroll
            for (int mt = 0; mt < 4; mt++)
#pragma unroll
                for (int nj = 0; nj < 8; nj++) {
                    int m = mt * 16 + (lane >> 2);
                    int cc = wn * 64 + nj * 8 + 2 * (lane & 3);
                    sT[m * 132 + cc]           = acc[mt][nj][0];
                    sT[m * 132 + cc + 1]       = acc[mt][nj][1];
                    sT[(m + 8) * 132 + cc]     = acc[mt][nj][2];
                    sT[(m + 8) * 132 + cc + 1] = acc[mt][nj][3];
                }
        }
        __syncthreads();
#pragma unroll
        for (int it = 0; it < 16; it++) {
            int idx = tid + it * 128;
            int row = idx >> 5, ch4 = (idx & 31) * 4;
            int tok = n0 + p * 64 + row;
            float4 vv = *(float4*)&sT[row * 132 + ch4];
            float4 bb = *(const float4*)&bias[c0 + ch4];
            vv.x += bb.x; vv.y += bb.y; vv.z += bb.z; vv.w += bb.w;
            *(float4*)&outp[(size_t)tok * 512 + c0 + ch4] = vv;
        }
        __syncthreads();
    }
}

// ---------------------------------------------------------------------------
extern "C" void kernel_launch(void* const* d_in, const int* in_sizes, int n_in,
                              void* d_out, int out_size)
{
    const float* x        = (const float*)d_in[0];
    const float* x_d      = (const float*)d_in[1];
    const float* W_qkv_r  = (const float*)d_in[2];
    const float* W_qkv_T  = (const float*)d_in[3];
    const float* temp_r   = (const float*)d_in[4];
    const float* temp_T   = (const float*)d_in[5];
    const float* W_proj_r = (const float*)d_in[6];
    const float* b_proj_r = (const float*)d_in[7];
    const float* W_proj_T = (const float*)d_in[8];
    const float* b_proj_T = (const float*)d_in[9];
    float* out = (float*)d_out;

    cudaFuncSetAttribute(qkv_mma_kernel,
        cudaFuncAttributeMaxDynamicSharedMemorySize, GEMM_SMEM);
    cudaFuncSetAttribute(proj_mma_kernel,
        cudaFuncAttributeMaxDynamicSharedMemorySize, GEMM_SMEM);
    cudaFuncSetAttribute(attn_gram_kernel,
        cudaFuncAttributeMaxDynamicSharedMemorySize, GRAM_SMEM);
    cudaFuncSetAttribute(attn_pv_kernel,
        cudaFuncAttributeMaxDynamicSharedMemorySize, PV_SMEM);

    prep_x_kernel<<<65536, 256>>>(x, x_d);
    prep_w_kernel<<<4096, 256>>>(W_qkv_r, W_qkv_T, W_proj_r, W_proj_T);

    {
        dim3 grid(12, 256, 2);    // c-tile fastest -> X slice L2-reused
        qkv_mma_kernel<<<grid, 128, GEMM_SMEM>>>();
    }
    {
        dim3 g1(8, 64, 2);
        attn_gram_kernel<<<g1, 256, GRAM_SMEM>>>();
        attn_softmax_kernel<<<128, 256>>>(temp_r, temp_T);
        dim3 g2(32, 64, 2);
        attn_pv_kernel<<<g2, 256, PV_SMEM>>>();
    }
    {
        dim3 grid(4, 32, 16);     // c-tile fastest
        proj_mma_kernel<<<grid, 128, GEMM_SMEM>>>(b_proj_r, b_proj_T, out);
    }
}

// round 16
// speedup vs baseline: 1.1913x; 1.1913x over previous
#include <cuda_runtime.h>
#include <cuda_fp16.h>
#include <math.h>
#include <stdint.h>

// ---------------------------------------------------------------------------
// ChannelCrossAttention — HMMA fp16 1-term. qkv: 128x192 CTA tile (warp
// 64x96, 4 warps, 2 CTA/SM — the validated register/occupancy sweet spot).
// proj: 128x128 @ 2 CTA/SM. Token-major q/k/v scratch; gram via
// ldmatrix.trans; warp softmax. Single merged prep kernel.
// ---------------------------------------------------------------------------

// packed 2xfp16 per u32
__device__ uint32_t g_x_h[2u * 32768u * 256u];     // [s][m][kpair]
__device__ uint32_t g_wq_h[2u * 1536u * 256u];     // [s][c][kpair]
__device__ uint32_t g_wp_h[2u * 512u * 256u];
// q/k/v token-major: [s][w 0..2][b][n 4096][cpair 256]
__device__ uint32_t g_qkv_h[2u * 3u * 8u * 4096u * 256u];
// attention out token-major: [s][b][n][kpair 256]
__device__ uint32_t g_att_h[2u * 8u * 4096u * 256u];
// per-channel sumsq partials: [s][w(q/k)][b][c 512][part 64]
__device__ float g_nrm[2u * 2u * 8u * 512u * 64u];
// Gram partials [g 128][chunk 8][64*64]
__device__ float g_pgram[128u * 8u * 4096u];
// P packed fp16 [g][d 64][epair 32]
__device__ uint32_t g_p_h[128u * 2048u];

// ---------------------------------------------------------------------------
__device__ __forceinline__ uint32_t smem_u32(const void* p) {
    uint32_t a;
    asm("{ .reg .u64 t; cvta.to.shared.u64 t, %1; cvt.u32.u64 %0, t; }" : "=r"(a) : "l"(p));
    return a;
}
__device__ __forceinline__ uint32_t swz(uint32_t off) { return off ^ (((off) >> 3) & 0x70); }

__device__ __forceinline__ void ldmx4(uint32_t& r0, uint32_t& r1, uint32_t& r2, uint32_t& r3,
                                      uint32_t addr) {
    asm volatile("ldmatrix.sync.aligned.m8n8.x4.shared.b16 {%0,%1,%2,%3}, [%4];"
        : "=r"(r0), "=r"(r1), "=r"(r2), "=r"(r3) : "r"(addr));
}
__device__ __forceinline__ void ldmx4t(uint32_t& r0, uint32_t& r1, uint32_t& r2, uint32_t& r3,
                                       uint32_t addr) {
    asm volatile("ldmatrix.sync.aligned.m8n8.x4.trans.shared.b16 {%0,%1,%2,%3}, [%4];"
        : "=r"(r0), "=r"(r1), "=r"(r2), "=r"(r3) : "r"(addr));
}
__device__ __forceinline__ void mma_h(float* c, const uint32_t* a, const uint32_t* b) {
    asm volatile("mma.sync.aligned.m16n8k16.row.col.f32.f16.f16.f32 "
        "{%0,%1,%2,%3}, {%4,%5,%6,%7}, {%8,%9}, {%0,%1,%2,%3};"
        : "+f"(c[0]), "+f"(c[1]), "+f"(c[2]), "+f"(c[3])
        : "r"(a[0]), "r"(a[1]), "r"(a[2]), "r"(a[3]), "r"(b[0]), "r"(b[1]));
}
#define CP_ASYNC16(dst, src) \
    asm volatile("cp.async.cg.shared.global [%0], [%1], 16;" :: "r"(dst), "l"(src))
#define CP_COMMIT() asm volatile("cp.async.commit_group;")
#define CP_WAIT0()  asm volatile("cp.async.wait_group 0;")
#define CP_WAIT1()  asm volatile("cp.async.wait_group 1;")

__device__ __forceinline__ uint32_t packh(__half a, __half b) {
    return (uint32_t)__half_as_ushort(a) | ((uint32_t)__half_as_ushort(b) << 16);
}
__device__ __forceinline__ uint32_t cvt1h(float a, float b) {
    return packh(__float2half_rn(a), __float2half_rn(b));
}

// qkv smem: stage = A 16K | B 24K = 40KB, 2 stages = 80KB (2 CTA -> 160KB/SM)
#define SK_A(st) ((st) * 40960 + 0)
#define SK_B(st) ((st) * 40960 + 16384)
#define QKV_SMEM (81920 + 1024)
// proj smem: stage = A 16K | B 16K = 32KB, 2 stages
#define SQ_A(st) ((st) * 32768 + 0)
#define SQ_B(st) ((st) * 32768 + 16384)
#define PROJ_SMEM (65536 + 1024)
// gram smem: stage = q 8K | k 8K = 16KB, 2 stages
#define SG_Q(st) ((st) * 16384 + 0)
#define SG_K(st) ((st) * 16384 + 8192)
#define GRAM_SMEM (32768 + 1024)
// pv smem: v 16K | P 8K
#define SP_V 0
#define SP_P 16384
#define PV_SMEM (24576 + 1024)

// ---------------------------------------------------------------------------
// Merged prep: X (vectorized) + both weight sets in one launch.
//   X region:  8388608 threads (each converts 4 fp32 -> 2 u32)
//   W region:  1048576 threads (TQ + TP)
// ---------------------------------------------------------------------------
#define PREP_X_THREADS 8388608
__global__ __launch_bounds__(256) void prep_kernel(
    const float* __restrict__ x, const float* __restrict__ x_d,
    const float* __restrict__ Wq_r, const float* __restrict__ Wq_T,
    const float* __restrict__ Wp_r, const float* __restrict__ Wp_T)
{
    int idx = blockIdx.x * 256 + threadIdx.x;
    if (idx < PREP_X_THREADS) {
        int s = idx >> 22;
        int r = idx & 0x3FFFFF;
        int m = r >> 7, kq = r & 127;          // kq = quad of fp32 (2 kpairs)
        const float* X = s ? x_d : x;
        float4 v = *(const float4*)&X[(size_t)m * 512 + kq * 4];
        uint2 o = make_uint2(cvt1h(v.x, v.y), cvt1h(v.z, v.w));
        *(uint2*)&g_x_h[((size_t)s * 32768 + m) * 256 + kq * 2] = o;
        return;
    }
    int wi = idx - PREP_X_THREADS;
    const int TQ = 2 * 1536 * 256;
    const int TP = 2 * 512 * 256;
    if (wi < TQ) {
        int s = wi / (1536 * 256);
        int r = wi % (1536 * 256);
        int c = r >> 8, kp = r & 255;
        const float* W = s ? Wq_T : Wq_r;
        g_wq_h[wi] = cvt1h(W[(size_t)(2 * kp) * 1536 + c],
                           W[(size_t)(2 * kp + 1) * 1536 + c]);
    } else if (wi < TQ + TP) {
        int i2 = wi - TQ;
        int s = i2 / (512 * 256);
        int r = i2 % (512 * 256);
        int c = r >> 8, kp = r & 255;
        const float* W = s ? Wp_T : Wp_r;
        g_wp_h[i2] = cvt1h(W[(size_t)(2 * kp) * 512 + c],
                           W[(size_t)(2 * kp + 1) * 512 + c]);
    }
}

// ---------------------------------------------------------------------------
// Kernel 1: qkv GEMM. CTA 128(m) x 192(c), 4 warps (wm2 x wn2), warp 64x96.
// grid (cTile 8, mTile 256, s 2), 128 threads, 2 CTA/SM.
// ---------------------------------------------------------------------------
__device__ __forceinline__ void fill_qkv(uint32_t sb, int st, int tid, int kp0,
    size_t aBase, size_t bBase)
{
#pragma unroll
    for (int it = 0; it < 8; it++) {
        int idx = tid + it * 128;          // 1024 lines for A (128 rows)
        int r = idx >> 3, c16 = idx & 7;
        uint32_t dsw = swz((uint32_t)(r * 128 + c16 * 16));
        CP_ASYNC16(sb + SK_A(st) + dsw, g_x_h + aBase + (size_t)r * 256 + kp0 + c16 * 4);
    }
#pragma unroll
    for (int it = 0; it < 12; it++) {
        int idx = tid + it * 128;          // 1536 lines for B (192 rows)
        int r = idx >> 3, c16 = idx & 7;
        uint32_t dsw = swz((uint32_t)(r * 128 + c16 * 16));
        CP_ASYNC16(sb + SK_B(st) + dsw, g_wq_h + bBase + (size_t)r * 256 + kp0 + c16 * 4);
    }
    CP_COMMIT();
}

__global__ __launch_bounds__(128, 2) void qkv_mma_kernel()
{
    extern __shared__ char dsm[];
    uint32_t sbr = smem_u32(dsm);
    uint32_t sb = (sbr + 1023) & ~1023u;
    char* ab = dsm + (sb - sbr);

    const int tid = threadIdx.x;
    const int wid = tid >> 5;
    const int lane = tid & 31;
    const int wm = wid & 1, wn = wid >> 1;     // 2 x 2
    const int s = blockIdx.z;
    const int m0 = blockIdx.y * 128;
    const int c0 = blockIdx.x * 192;
    const int b = m0 >> 12, n0 = m0 & 4095;

    const size_t aBase = ((size_t)s * 32768 + m0) * 256;
    const size_t bBase = ((size_t)s * 1536 + c0) * 256;

    float acc[4][12][4];
#pragma unroll
    for (int i = 0; i < 4; i++)
#pragma unroll
        for (int j = 0; j < 12; j++)
#pragma unroll
            for (int r = 0; r < 4; r++) acc[i][j][r] = 0.f;

    const int aRow  = wm * 64 + (lane & 15);
    const int aColb = (lane >> 4) * 16;
    const int bRow  = wn * 96 + (lane & 7) + ((lane >> 4) & 1) * 8;
    const int bColb = ((lane >> 3) & 1) * 16;

    fill_qkv(sb, 0, tid, 0, aBase, bBase);
    for (int c = 0; c < 8; c++) {
        int st = c & 1;
        if (c < 7) fill_qkv(sb, st ^ 1, tid, (c + 1) * 32, aBase, bBase);
        if (c < 7) CP_WAIT1(); else CP_WAIT0();
        __syncthreads();
#pragma unroll
        for (int kk = 0; kk < 4; kk++) {
            uint32_t ah[4][4], bf[12][2];
#pragma unroll
            for (int mt = 0; mt < 4; mt++)
                ldmx4(ah[mt][0], ah[mt][1], ah[mt][2], ah[mt][3],
                      sb + SK_A(st) + swz((uint32_t)((aRow + mt * 16) * 128 + aColb + kk * 32)));
#pragma unroll
            for (int j = 0; j < 6; j++)
                ldmx4(bf[2 * j][0], bf[2 * j][1], bf[2 * j + 1][0], bf[2 * j + 1][1],
                      sb + SK_B(st) + swz((uint32_t)((bRow + j * 16) * 128 + bColb + kk * 32)));
#pragma unroll
            for (int mt = 0; mt < 4; mt++)
#pragma unroll
                for (int nj = 0; nj < 12; nj++)
                    mma_h(acc[mt][nj], ah[mt], bf[nj]);
        }
        __syncthreads();
    }

    // epilogue: frags -> sbuf[t 128][cp 96] (pitch 100) + norms (q/k channels)
    uint32_t* sbuf = (uint32_t*)ab;
#pragma unroll
    for (int nj = 0; nj < 12; nj++) {
        int cch = c0 + wn * 96 + nj * 8 + 2 * (lane & 3);   // channel of frag cols
        int whichc = cch >> 9;
        float r2a = 0.f, r2b = 0.f;
#pragma unroll
        for (int mt = 0; mt < 4; mt++) {
            int tl = wm * 64 + mt * 16 + (lane >> 2);
            int cpl = wn * 48 + nj * 4 + (lane & 3);        // local cpair 0..95
            sbuf[tl * 100 + cpl]       = cvt1h(acc[mt][nj][0], acc[mt][nj][1]);
            sbuf[(tl + 8) * 100 + cpl] = cvt1h(acc[mt][nj][2], acc[mt][nj][3]);
            if (whichc < 2) {
                r2a += acc[mt][nj][0] * acc[mt][nj][0] + acc[mt][nj][2] * acc[mt][nj][2];
                r2b += acc[mt][nj][1] * acc[mt][nj][1] + acc[mt][nj][3] * acc[mt][nj][3];
            }
        }
        if (whichc < 2) {
            r2a += __shfl_xor_sync(0xFFFFFFFFu, r2a, 4);
            r2b += __shfl_xor_sync(0xFFFFFFFFu, r2b, 4);
            r2a += __shfl_xor_sync(0xFFFFFFFFu, r2a, 8);
            r2b += __shfl_xor_sync(0xFFFFFFFFu, r2b, 8);
            r2a += __shfl_xor_sync(0xFFFFFFFFu, r2a, 16);
            r2b += __shfl_xor_sync(0xFFFFFFFFu, r2b, 16);
            if (lane < 4) {
                int remc = (c0 + wn * 96 + nj * 8 + 2 * lane) & 511;
                int part = (n0 >> 7) * 2 + wm;
                size_t nb = ((((size_t)(s * 2 + whichc)) * 8 + b) * 512 + remc) * 64 + part;
                g_nrm[nb]      = r2a;
                g_nrm[nb + 64] = r2b;
            }
        }
    }
    __syncthreads();

    // coalesced copy sbuf -> g_qkv_h; which computed per 16B chunk
    const int gcp0 = c0 >> 1;       // global cpair of tile start (multiple of 96)
#pragma unroll
    for (int it = 0; it < 24; it++) {
        int idx = tid + it * 128;       // 3072 x 16B chunks
        int row = idx / 24;
        int q4 = idx - row * 24;        // 0..23
        int gcp = gcp0 + q4 * 4;        // aligned, never straddles 256-boundary
        int which = gcp >> 8;
        int rem = gcp & 255;
        uint4 v4 = *(uint4*)&sbuf[row * 100 + q4 * 4];
        size_t rb = ((size_t)((s * 3 + which) * 8 + b)) * 4096;
        *(uint4*)&g_qkv_h[(rb + n0 + row) * 256 + rem] = v4;
    }
}

// ---------------------------------------------------------------------------
// Kernel 2a: Gram partials via ldmatrix.trans. grid (chunk 8, bh 64, s 2)
// ---------------------------------------------------------------------------
__global__ __launch_bounds__(256) void attn_gram_kernel()
{
    extern __shared__ char dsm[];
    uint32_t sbr = smem_u32(dsm);
    uint32_t sb = (sbr + 1023) & ~1023u;

    const int tid = threadIdx.x;
    const int wid = tid >> 5;
    const int lane = tid & 31;
    const int wm = wid & 1, wn = wid >> 1;
    const int chunk = blockIdx.x;
    const int bh = blockIdx.y;
    const int s = blockIdx.z;
    const int b = bh >> 3, h = bh & 7;
    const int so = s ^ 1;
    const int g = s * 64 + bh;

    const size_t qb = ((size_t)((s  * 3 + 0) * 8 + b)) * 4096;
    const size_t kb = ((size_t)((so * 3 + 1) * 8 + b)) * 4096;

    float acc[2][2][4];
#pragma unroll
    for (int i = 0; i < 2; i++)
#pragma unroll
        for (int j = 0; j < 2; j++)
#pragma unroll
            for (int r = 0; r < 4; r++) acc[i][j][r] = 0.f;

    auto fill_sub = [&](int st, int sub) {
        int tok0 = chunk * 512 + sub * 64;
#pragma unroll
        for (int it = 0; it < 2; it++) {
            int idx = tid + it * 256;
            int r = idx >> 3, c16 = idx & 7;
            uint32_t dsw = swz((uint32_t)(r * 128 + c16 * 16));
            CP_ASYNC16(sb + SG_Q(st) + dsw, g_qkv_h + (qb + tok0 + r) * 256 + h * 32 + c16 * 4);
            CP_ASYNC16(sb + SG_K(st) + dsw, g_qkv_h + (kb + tok0 + r) * 256 + h * 32 + c16 * 4);
        }
        CP_COMMIT();
    };

    const int aTrowOff = ((lane >> 4) & 1) * 8 + (lane & 7);
    const int aDcolOff = ((lane >> 3) & 1) * 8;
    const int bTrowOff = ((lane >> 3) & 1) * 8 + (lane & 7);
    const int bEcolOff = ((lane >> 4) & 1) * 8;

    fill_sub(0, 0);
    for (int sub = 0; sub < 8; sub++) {
        int st = sub & 1;
        if (sub < 7) fill_sub(st ^ 1, sub + 1);
        if (sub < 7) CP_WAIT1(); else CP_WAIT0();
        __syncthreads();
#pragma unroll
        for (int kk = 0; kk < 4; kk++) {
            const int t0 = kk * 16;
            uint32_t qh[2][4], kf[2][2];
#pragma unroll
            for (int mt = 0; mt < 2; mt++) {
                int d0 = wm * 32 + mt * 16;
                ldmx4t(qh[mt][0], qh[mt][1], qh[mt][2], qh[mt][3],
                       sb + SG_Q(st) + swz((uint32_t)((t0 + aTrowOff) * 128 + (d0 + aDcolOff) * 2)));
            }
            {
                int e0 = wn * 16;
                ldmx4t(kf[0][0], kf[0][1], kf[1][0], kf[1][1],
                       sb + SG_K(st) + swz((uint32_t)((t0 + bTrowOff) * 128 + (e0 + bEcolOff) * 2)));
            }
#pragma unroll
            for (int mt = 0; mt < 2; mt++)
#pragma unroll
                for (int nt = 0; nt < 2; nt++)
                    mma_h(acc[mt][nt], qh[mt], kf[nt]);
        }
        __syncthreads();
    }

    const size_t base = (size_t)(g * 8 + chunk) * 4096;
#pragma unroll
    for (int mt = 0; mt < 2; mt++)
#pragma unroll
        for (int nt = 0; nt < 2; nt++) {
            int m = wm * 32 + mt * 16 + (lane >> 2);
            int col = wn * 16 + nt * 8 + 2 * (lane & 3);
            *(float2*)&g_pgram[base + m * 64 + col] = make_float2(acc[mt][nt][0], acc[mt][nt][1]);
            *(float2*)&g_pgram[base + (m + 8) * 64 + col] = make_float2(acc[mt][nt][2], acc[mt][nt][3]);
        }
}

// ---------------------------------------------------------------------------
// Kernel 2b: reduce partials + norms, softmax (warp-parallel), emit P fp16
// ---------------------------------------------------------------------------
__global__ __launch_bounds__(256) void attn_softmax_kernel(
    const float* __restrict__ temp_rgb, const float* __restrict__ temp_T)
{
    const int g = blockIdx.x;
    const int s = g >> 6;
    const int bh = g & 63;
    const int b = bh >> 3, h = bh & 7;
    const int so = s ^ 1;
    const float temp = (s ? temp_T : temp_rgb)[h];

    __shared__ float qinv[64], kinv[64];
    const int tid = threadIdx.x;

    if (tid < 64) {
        float sq = 0.f;
        size_t nb = (((size_t)(s * 2 + 0) * 8 + b) * 512 + h * 64 + tid) * 64;
#pragma unroll
        for (int t = 0; t < 64; t++) sq += g_nrm[nb + t];
        qinv[tid] = 1.f / fmaxf(sqrtf(sq), 1e-12f);
    } else if (tid < 128) {
        float sk = 0.f;
        size_t nb = (((size_t)(so * 2 + 1) * 8 + b) * 512 + h * 64 + tid - 64) * 64;
#pragma unroll
        for (int t = 0; t < 64; t++) sk += g_nrm[nb + t];
        kinv[tid - 64] = 1.f / fmaxf(sqrtf(sk), 1e-12f);
    }
    __syncthreads();

    const int wid = tid >> 5, lane = tid & 31;
    const int j0 = lane * 2;
    const float ki0 = kinv[j0], ki1 = kinv[j0 + 1];
#pragma unroll
    for (int r = 0; r < 8; r++) {
        int d = wid * 8 + r;
        float v0 = 0.f, v1 = 0.f;
#pragma unroll
        for (int c = 0; c < 8; c++) {
            float2 pv = *(const float2*)&g_pgram[(size_t)(g * 8 + c) * 4096 + d * 64 + j0];
            v0 += pv.x; v1 += pv.y;
        }
        float sc = temp * qinv[d];
        v0 *= sc * ki0;
        v1 *= sc * ki1;
        float mx = fmaxf(v0, v1);
#pragma unroll
        for (int o = 16; o; o >>= 1) mx = fmaxf(mx, __shfl_xor_sync(0xFFFFFFFFu, mx, o));
        float e0 = __expf(v0 - mx), e1 = __expf(v1 - mx);
        float sm = e0 + e1;
#pragma unroll
        for (int o = 16; o; o >>= 1) sm += __shfl_xor_sync(0xFFFFFFFFu, sm, o);
        float inv = 1.f / sm;
        g_p_h[(size_t)g * 2048 + d * 32 + lane] = cvt1h(e0 * inv, e1 * inv);
    }
}

// ---------------------------------------------------------------------------
// Kernel 2c: out = P @ v. grid (tile 32, bh 64, s 2)
// ---------------------------------------------------------------------------
__global__ __launch_bounds__(256) void attn_pv_kernel()
{
    extern __shared__ char dsm[];
    uint32_t sbr = smem_u32(dsm);
    uint32_t sb = (sbr + 1023) & ~1023u;

    const int tid = threadIdx.x;
    const int wid = tid >> 5;
    const int lane = tid & 31;
    const int wm = wid & 1, wn = wid >> 1;
    const int n0 = blockIdx.x * 128;
    const int bh = blockIdx.y;
    const int s = blockIdx.z;
    const int b = bh >> 3, h = bh & 7;
    const int so = s ^ 1;
    const int g = s * 64 + bh;
    const size_t vb = ((size_t)((so * 3 + 2) * 8 + b)) * 4096;

#pragma unroll
    for (int it = 0; it < 4; it++) {
        int idx = tid + it * 256;
        int r = idx >> 3, c16 = idx & 7;
        uint32_t dsw = swz((uint32_t)(r * 128 + c16 * 16));
        CP_ASYNC16(sb + SP_V + dsw, g_qkv_h + (vb + n0 + r) * 256 + h * 32 + c16 * 4);
    }
#pragma unroll
    for (int it = 0; it < 2; it++) {
        int idx = tid + it * 256;
        int r = idx >> 3, c16 = idx & 7;
        uint32_t dsw = swz((uint32_t)(r * 128 + c16 * 16));
        CP_ASYNC16(sb + SP_P + dsw, g_p_h + (size_t)g * 2048 + r * 32 + c16 * 4);
    }
    CP_COMMIT();
    CP_WAIT0();
    __syncthreads();

    float acc[4][2][4];
#pragma unroll
    for (int i = 0; i < 4; i++)
#pragma unroll
        for (int j = 0; j < 2; j++)
#pragma unroll
            for (int r = 0; r < 4; r++) acc[i][j][r] = 0.f;

    const int aRow  = wm * 64 + (lane & 15);
    const int aColb = (lane >> 4) * 16;
    const int bRow  = wn * 16 + (lane & 7) + ((lane >> 4) & 1) * 8;
    const int bColb = ((lane >> 3) & 1) * 16;

#pragma unroll
    for (int kk = 0; kk < 4; kk++) {
        uint32_t vh[4][4], pf[2][2];
#pragma unroll
        for (int mt = 0; mt < 4; mt++)
            ldmx4(vh[mt][0], vh[mt][1], vh[mt][2], vh[mt][3],
                  sb + SP_V + swz((uint32_t)((aRow + mt * 16) * 128 + aColb + kk * 32)));
        ldmx4(pf[0][0], pf[0][1], pf[1][0], pf[1][1],
              sb + SP_P + swz((uint32_t)(bRow * 128 + bColb + kk * 32)));
#pragma unroll
        for (int mt = 0; mt < 4; mt++)
#pragma unroll
            for (int nt = 0; nt < 2; nt++)
                mma_h(acc[mt][nt], vh[mt], pf[nt]);
    }

    const size_t ob = (size_t)(s * 8 + b) * 4096;
#pragma unroll
    for (int mt = 0; mt < 4; mt++) {
        int t = n0 + wm * 64 + mt * 16 + (lane >> 2);
#pragma unroll
        for (int nt = 0; nt < 2; nt++) {
            int dp = wn * 8 + nt * 4 + (lane & 3);
            size_t a0 = (ob + t) * 256 + h * 32 + dp;
            g_att_h[a0]           = cvt1h(acc[mt][nt][0], acc[mt][nt][1]);
            g_att_h[a0 + 8 * 256] = cvt1h(acc[mt][nt][2], acc[mt][nt][3]);
        }
    }
}

// ---------------------------------------------------------------------------
// Kernel 3: proj GEMM. grid (cTile 4, nTile 32, sb 16), 128 threads, 2 CTA/SM.
// ---------------------------------------------------------------------------
__device__ __forceinline__ void fill_proj(uint32_t sb, int st, int tid, int kp0,
    size_t aBase, size_t bBase)
{
#pragma unroll
    for (int it = 0; it < 8; it++) {
        int idx = tid + it * 128;
        int r = idx >> 3, c16 = idx & 7;
        uint32_t dsw = swz((uint32_t)(r * 128 + c16 * 16));
        CP_ASYNC16(sb + SQ_A(st) + dsw, g_att_h + aBase + (size_t)r * 256 + kp0 + c16 * 4);
    }
#pragma unroll
    for (int it = 0; it < 8; it++) {
        int idx = tid + it * 128;
        int r = idx >> 3, c16 = idx & 7;
        uint32_t dsw = swz((uint32_t)(r * 128 + c16 * 16));
        CP_ASYNC16(sb + SQ_B(st) + dsw, g_wp_h + bBase + (size_t)r * 256 + kp0 + c16 * 4);
    }
    CP_COMMIT();
}

__global__ __launch_bounds__(128, 2) void proj_mma_kernel(
    const float* __restrict__ br, const float* __restrict__ bt,
    float* __restrict__ out)
{
    extern __shared__ char dsm[];
    uint32_t sbr = smem_u32(dsm);
    uint32_t sb = (sbr + 1023) & ~1023u;
    char* ab = dsm + (sb - sbr);

    const int tid = threadIdx.x;
    const int wid = tid >> 5;
    const int lane = tid & 31;
    const int wm = wid & 1, wn = wid >> 1;
    const int z = blockIdx.z;
    const int s = z >> 3, b = z & 7;
    const float* __restrict__ bias = s ? bt : br;
    const int n0 = blockIdx.y * 128;
    const int c0 = blockIdx.x * 128;

    const size_t aBase = (((size_t)(s * 8 + b)) * 4096 + n0) * 256;
    const size_t bBase = ((size_t)s * 512 + c0) * 256;

    float acc[4][8][4];
#pragma unroll
    for (int i = 0; i < 4; i++)
#pragma unroll
        for (int j = 0; j < 8; j++)
#pragma unroll
            for (int r = 0; r < 4; r++) acc[i][j][r] = 0.f;

    const int aRow  = wm * 64 + (lane & 15);
    const int aColb = (lane >> 4) * 16;
    const int bRow  = wn * 64 + (lane & 7) + ((lane >> 4) & 1) * 8;
    const int bColb = ((lane >> 3) & 1) * 16;

    fill_proj(sb, 0, tid, 0, aBase, bBase);
    for (int c = 0; c < 8; c++) {
        int st = c & 1;
        if (c < 7) fill_proj(sb, st ^ 1, tid, (c + 1) * 32, aBase, bBase);
        if (c < 7) CP_WAIT1(); else CP_WAIT0();
        __syncthreads();
#pragma unroll
        for (int kk = 0; kk < 4; kk++) {
            uint32_t ah[4][4], bf[8][2];
#pragma unroll
            for (int mt = 0; mt < 4; mt++)
                ldmx4(ah[mt][0], ah[mt][1], ah[mt][2], ah[mt][3],
                      sb + SQ_A(st) + swz((uint32_t)((aRow + mt * 16) * 128 + aColb + kk * 32)));
#pragma unroll
            for (int j = 0; j < 4; j++)
                ldmx4(bf[2 * j][0], bf[2 * j][1], bf[2 * j + 1][0], bf[2 * j + 1][1],
                      sb + SQ_B(st) + swz((uint32_t)((bRow + j * 16) * 128 + bColb + kk * 32)));
#pragma unroll
            for (int mt = 0; mt < 4; mt++)
#pragma unroll
                for (int nj = 0; nj < 8; nj++)
                    mma_h(acc[mt][nj], ah[mt], bf[nj]);
        }
        __syncthreads();
    }

    // epilogue: [token][channel] + bias via smem transpose (2 passes over wm)
    float* sT = (float*)ab;   // 64 x 132 fp32
    float* outp = out + (size_t)(s * 8 + b) * 2097152;
#pragma unroll
    for (int p = 0; p < 2; p++) {
        if (wm == p) {
#pragma unroll
            for (int mt = 0; mt < 4; mt++)
#pragma unroll
                for (int nj = 0; nj < 8; nj++) {
                    int m = mt * 16 + (lane >> 2);
                    int cc = wn * 64 + nj * 8 + 2 * (lane & 3);
                    sT[m * 132 + cc]           = acc[mt][nj][0];
                    sT[m * 132 + cc + 1]       = acc[mt][nj][1];
                    sT[(m + 8) * 132 + cc]     = acc[mt][nj][2];
                    sT[(m + 8) * 132 + cc + 1] = acc[mt][nj][3];
                }
        }
        __syncthreads();
#pragma unroll
        for (int it = 0; it < 16; it++) {
            int idx = tid + it * 128;
            int row = idx >> 5, ch4 = (idx & 31) * 4;
            int tok = n0 + p * 64 + row;
            float4 vv = *(float4*)&sT[row * 132 + ch4];
            float4 bb = *(const float4*)&bias[c0 + ch4];
            vv.x += bb.x; vv.y += bb.y; vv.z += bb.z; vv.w += bb.w;
            *(float4*)&outp[(size_t)tok * 512 + c0 + ch4] = vv;
        }
        __syncthreads();
    }
}

// ---------------------------------------------------------------------------
extern "C" void kernel_launch(void* const* d_in, const int* in_sizes, int n_in,
                              void* d_out, int out_size)
{
    const float* x        = (const float*)d_in[0];
    const float* x_d      = (const float*)d_in[1];
    const float* W_qkv_r  = (const float*)d_in[2];
    const float* W_qkv_T  = (const float*)d_in[3];
    const float* temp_r   = (const float*)d_in[4];
    const float* temp_T   = (const float*)d_in[5];
    const float* W_proj_r = (const float*)d_in[6];
    const float* b_proj_r = (const float*)d_in[7];
    const float* W_proj_T = (const float*)d_in[8];
    const float* b_proj_T = (const float*)d_in[9];
    float* out = (float*)d_out;

    cudaFuncSetAttribute(qkv_mma_kernel,
        cudaFuncAttributeMaxDynamicSharedMemorySize, QKV_SMEM);
    cudaFuncSetAttribute(proj_mma_kernel,
        cudaFuncAttributeMaxDynamicSharedMemorySize, PROJ_SMEM);
    cudaFuncSetAttribute(attn_gram_kernel,
        cudaFuncAttributeMaxDynamicSharedMemorySize, GRAM_SMEM);
    cudaFuncSetAttribute(attn_pv_kernel,
        cudaFuncAttributeMaxDynamicSharedMemorySize, PV_SMEM);

    // merged prep: X (8388608 threads) + weights (1048576 threads)
    prep_kernel<<<(PREP_X_THREADS + 2 * 1536 * 256 + 2 * 512 * 256 + 255) / 256, 256>>>(
        x, x_d, W_qkv_r, W_qkv_T, W_proj_r, W_proj_T);

    {
        dim3 grid(8, 256, 2);     // c-tile fastest -> X slice L2-reused
        qkv_mma_kernel<<<grid, 128, QKV_SMEM>>>();
    }
    {
        dim3 g1(8, 64, 2);
        attn_gram_kernel<<<g1, 256, GRAM_SMEM>>>();
        attn_softmax_kernel<<<128, 256>>>(temp_r, temp_T);
        dim3 g2(32, 64, 2);
        attn_pv_kernel<<<g2, 256, PV_SMEM>>>();
    }
    {
        dim3 grid(4, 32, 16);     // c-tile fastest
        proj_mma_kernel<<<grid, 128, PROJ_SMEM>>>(b_proj_r, b_proj_T, out);
    }
}

// round 17
// speedup vs baseline: 1.2015x; 1.0085x over previous
#include <cuda_runtime.h>
#include <cuda_fp16.h>
#include <math.h>
#include <stdint.h>

// ---------------------------------------------------------------------------
// ChannelCrossAttention — HMMA fp16 1-term. qkv: 128x192 CTA tile (warp
// 64x96, 4 warps, 2 CTA/SM). proj: 128x128 @ 2 CTA/SM. Token-major q/k/v;
// gram via ldmatrix.trans; split softmax (grid 128x2); pv 2 tiles/CTA.
// ---------------------------------------------------------------------------

// packed 2xfp16 per u32
__device__ uint32_t g_x_h[2u * 32768u * 256u];     // [s][m][kpair]
__device__ uint32_t g_wq_h[2u * 1536u * 256u];     // [s][c][kpair]
__device__ uint32_t g_wp_h[2u * 512u * 256u];
// q/k/v token-major: [s][w 0..2][b][n 4096][cpair 256]
__device__ uint32_t g_qkv_h[2u * 3u * 8u * 4096u * 256u];
// attention out token-major: [s][b][n][kpair 256]
__device__ uint32_t g_att_h[2u * 8u * 4096u * 256u];
// per-channel sumsq partials: [s][w(q/k)][b][c 512][part 64]
__device__ float g_nrm[2u * 2u * 8u * 512u * 64u];
// Gram partials [g 128][chunk 8][64*64]
__device__ float g_pgram[128u * 8u * 4096u];
// P packed fp16 [g][d 64][epair 32]
__device__ uint32_t g_p_h[128u * 2048u];

// ---------------------------------------------------------------------------
__device__ __forceinline__ uint32_t smem_u32(const void* p) {
    uint32_t a;
    asm("{ .reg .u64 t; cvta.to.shared.u64 t, %1; cvt.u32.u64 %0, t; }" : "=r"(a) : "l"(p));
    return a;
}
__device__ __forceinline__ uint32_t swz(uint32_t off) { return off ^ (((off) >> 3) & 0x70); }

__device__ __forceinline__ void ldmx4(uint32_t& r0, uint32_t& r1, uint32_t& r2, uint32_t& r3,
                                      uint32_t addr) {
    asm volatile("ldmatrix.sync.aligned.m8n8.x4.shared.b16 {%0,%1,%2,%3}, [%4];"
        : "=r"(r0), "=r"(r1), "=r"(r2), "=r"(r3) : "r"(addr));
}
__device__ __forceinline__ void ldmx4t(uint32_t& r0, uint32_t& r1, uint32_t& r2, uint32_t& r3,
                                       uint32_t addr) {
    asm volatile("ldmatrix.sync.aligned.m8n8.x4.trans.shared.b16 {%0,%1,%2,%3}, [%4];"
        : "=r"(r0), "=r"(r1), "=r"(r2), "=r"(r3) : "r"(addr));
}
__device__ __forceinline__ void mma_h(float* c, const uint32_t* a, const uint32_t* b) {
    asm volatile("mma.sync.aligned.m16n8k16.row.col.f32.f16.f16.f32 "
        "{%0,%1,%2,%3}, {%4,%5,%6,%7}, {%8,%9}, {%0,%1,%2,%3};"
        : "+f"(c[0]), "+f"(c[1]), "+f"(c[2]), "+f"(c[3])
        : "r"(a[0]), "r"(a[1]), "r"(a[2]), "r"(a[3]), "r"(b[0]), "r"(b[1]));
}
#define CP_ASYNC16(dst, src) \
    asm volatile("cp.async.cg.shared.global [%0], [%1], 16;" :: "r"(dst), "l"(src))
#define CP_COMMIT() asm volatile("cp.async.commit_group;")
#define CP_WAIT0()  asm volatile("cp.async.wait_group 0;")
#define CP_WAIT1()  asm volatile("cp.async.wait_group 1;")

__device__ __forceinline__ uint32_t packh(__half a, __half b) {
    return (uint32_t)__half_as_ushort(a) | ((uint32_t)__half_as_ushort(b) << 16);
}
__device__ __forceinline__ uint32_t cvt1h(float a, float b) {
    return packh(__float2half_rn(a), __float2half_rn(b));
}

// qkv smem: stage = A 16K | B 24K = 40KB, 2 stages = 80KB (2 CTA -> 160KB/SM)
#define SK_A(st) ((st) * 40960 + 0)
#define SK_B(st) ((st) * 40960 + 16384)
#define QKV_SMEM (81920 + 1024)
// proj smem: stage = A 16K | B 16K = 32KB, 2 stages
#define SQ_A(st) ((st) * 32768 + 0)
#define SQ_B(st) ((st) * 32768 + 16384)
#define PROJ_SMEM (65536 + 1024)
// gram smem: stage = q 8K | k 8K = 16KB, 2 stages
#define SG_Q(st) ((st) * 16384 + 0)
#define SG_K(st) ((st) * 16384 + 8192)
#define GRAM_SMEM (32768 + 1024)
// pv smem: v 2x16K (double buffer) | P 8K
#define SP_V(t) ((t) * 16384)
#define SP_P 32768
#define PV_SMEM (40960 + 1024)

// ---------------------------------------------------------------------------
// Merged prep: X (vectorized) + both weight sets in one launch.
// ---------------------------------------------------------------------------
#define PREP_X_THREADS 8388608
__global__ __launch_bounds__(256) void prep_kernel(
    const float* __restrict__ x, const float* __restrict__ x_d,
    const float* __restrict__ Wq_r, const float* __restrict__ Wq_T,
    const float* __restrict__ Wp_r, const float* __restrict__ Wp_T)
{
    int idx = blockIdx.x * 256 + threadIdx.x;
    if (idx < PREP_X_THREADS) {
        int s = idx >> 22;
        int r = idx & 0x3FFFFF;
        int m = r >> 7, kq = r & 127;
        const float* X = s ? x_d : x;
        float4 v = *(const float4*)&X[(size_t)m * 512 + kq * 4];
        uint2 o = make_uint2(cvt1h(v.x, v.y), cvt1h(v.z, v.w));
        *(uint2*)&g_x_h[((size_t)s * 32768 + m) * 256 + kq * 2] = o;
        return;
    }
    int wi = idx - PREP_X_THREADS;
    const int TQ = 2 * 1536 * 256;
    const int TP = 2 * 512 * 256;
    if (wi < TQ) {
        int s = wi / (1536 * 256);
        int r = wi % (1536 * 256);
        int c = r >> 8, kp = r & 255;
        const float* W = s ? Wq_T : Wq_r;
        g_wq_h[wi] = cvt1h(W[(size_t)(2 * kp) * 1536 + c],
                           W[(size_t)(2 * kp + 1) * 1536 + c]);
    } else if (wi < TQ + TP) {
        int i2 = wi - TQ;
        int s = i2 / (512 * 256);
        int r = i2 % (512 * 256);
        int c = r >> 8, kp = r & 255;
        const float* W = s ? Wp_T : Wp_r;
        g_wp_h[i2] = cvt1h(W[(size_t)(2 * kp) * 512 + c],
                           W[(size_t)(2 * kp + 1) * 512 + c]);
    }
}

// ---------------------------------------------------------------------------
// Kernel 1: qkv GEMM. CTA 128(m) x 192(c), warp 64x96, 2 CTA/SM.
// ---------------------------------------------------------------------------
__device__ __forceinline__ void fill_qkv(uint32_t sb, int st, int tid, int kp0,
    size_t aBase, size_t bBase)
{
#pragma unroll
    for (int it = 0; it < 8; it++) {
        int idx = tid + it * 128;
        int r = idx >> 3, c16 = idx & 7;
        uint32_t dsw = swz((uint32_t)(r * 128 + c16 * 16));
        CP_ASYNC16(sb + SK_A(st) + dsw, g_x_h + aBase + (size_t)r * 256 + kp0 + c16 * 4);
    }
#pragma unroll
    for (int it = 0; it < 12; it++) {
        int idx = tid + it * 128;
        int r = idx >> 3, c16 = idx & 7;
        uint32_t dsw = swz((uint32_t)(r * 128 + c16 * 16));
        CP_ASYNC16(sb + SK_B(st) + dsw, g_wq_h + bBase + (size_t)r * 256 + kp0 + c16 * 4);
    }
    CP_COMMIT();
}

__global__ __launch_bounds__(128, 2) void qkv_mma_kernel()
{
    extern __shared__ char dsm[];
    uint32_t sbr = smem_u32(dsm);
    uint32_t sb = (sbr + 1023) & ~1023u;
    char* ab = dsm + (sb - sbr);

    const int tid = threadIdx.x;
    const int wid = tid >> 5;
    const int lane = tid & 31;
    const int wm = wid & 1, wn = wid >> 1;
    const int s = blockIdx.z;
    const int m0 = blockIdx.y * 128;
    const int c0 = blockIdx.x * 192;
    const int b = m0 >> 12, n0 = m0 & 4095;

    const size_t aBase = ((size_t)s * 32768 + m0) * 256;
    const size_t bBase = ((size_t)s * 1536 + c0) * 256;

    float acc[4][12][4];
#pragma unroll
    for (int i = 0; i < 4; i++)
#pragma unroll
        for (int j = 0; j < 12; j++)
#pragma unroll
            for (int r = 0; r < 4; r++) acc[i][j][r] = 0.f;

    const int aRow  = wm * 64 + (lane & 15);
    const int aColb = (lane >> 4) * 16;
    const int bRow  = wn * 96 + (lane & 7) + ((lane >> 4) & 1) * 8;
    const int bColb = ((lane >> 3) & 1) * 16;

    fill_qkv(sb, 0, tid, 0, aBase, bBase);
    for (int c = 0; c < 8; c++) {
        int st = c & 1;
        if (c < 7) fill_qkv(sb, st ^ 1, tid, (c + 1) * 32, aBase, bBase);
        if (c < 7) CP_WAIT1(); else CP_WAIT0();
        __syncthreads();
#pragma unroll
        for (int kk = 0; kk < 4; kk++) {
            uint32_t ah[4][4], bf[12][2];
#pragma unroll
            for (int mt = 0; mt < 4; mt++)
                ldmx4(ah[mt][0], ah[mt][1], ah[mt][2], ah[mt][3],
                      sb + SK_A(st) + swz((uint32_t)((aRow + mt * 16) * 128 + aColb + kk * 32)));
#pragma unroll
            for (int j = 0; j < 6; j++)
                ldmx4(bf[2 * j][0], bf[2 * j][1], bf[2 * j + 1][0], bf[2 * j + 1][1],
                      sb + SK_B(st) + swz((uint32_t)((bRow + j * 16) * 128 + bColb + kk * 32)));
#pragma unroll
            for (int mt = 0; mt < 4; mt++)
#pragma unroll
                for (int nj = 0; nj < 12; nj++)
                    mma_h(acc[mt][nj], ah[mt], bf[nj]);
        }
        __syncthreads();
    }

    // epilogue: frags -> sbuf[t 128][cp 96] (pitch 100) + norms (q/k channels)
    uint32_t* sbuf = (uint32_t*)ab;
#pragma unroll
    for (int nj = 0; nj < 12; nj++) {
        int cch = c0 + wn * 96 + nj * 8 + 2 * (lane & 3);
        int whichc = cch >> 9;
        float r2a = 0.f, r2b = 0.f;
#pragma unroll
        for (int mt = 0; mt < 4; mt++) {
            int tl = wm * 64 + mt * 16 + (lane >> 2);
            int cpl = wn * 48 + nj * 4 + (lane & 3);
            sbuf[tl * 100 + cpl]       = cvt1h(acc[mt][nj][0], acc[mt][nj][1]);
            sbuf[(tl + 8) * 100 + cpl] = cvt1h(acc[mt][nj][2], acc[mt][nj][3]);
            if (whichc < 2) {
                r2a += acc[mt][nj][0] * acc[mt][nj][0] + acc[mt][nj][2] * acc[mt][nj][2];
                r2b += acc[mt][nj][1] * acc[mt][nj][1] + acc[mt][nj][3] * acc[mt][nj][3];
            }
        }
        if (whichc < 2) {
            r2a += __shfl_xor_sync(0xFFFFFFFFu, r2a, 4);
            r2b += __shfl_xor_sync(0xFFFFFFFFu, r2b, 4);
            r2a += __shfl_xor_sync(0xFFFFFFFFu, r2a, 8);
            r2b += __shfl_xor_sync(0xFFFFFFFFu, r2b, 8);
            r2a += __shfl_xor_sync(0xFFFFFFFFu, r2a, 16);
            r2b += __shfl_xor_sync(0xFFFFFFFFu, r2b, 16);
            if (lane < 4) {
                int remc = (c0 + wn * 96 + nj * 8 + 2 * lane) & 511;
                int part = (n0 >> 7) * 2 + wm;
                size_t nb = ((((size_t)(s * 2 + whichc)) * 8 + b) * 512 + remc) * 64 + part;
                g_nrm[nb]      = r2a;
                g_nrm[nb + 64] = r2b;
            }
        }
    }
    __syncthreads();

    const int gcp0 = c0 >> 1;
#pragma unroll
    for (int it = 0; it < 24; it++) {
        int idx = tid + it * 128;
        int row = idx / 24;
        int q4 = idx - row * 24;
        int gcp = gcp0 + q4 * 4;
        int which = gcp >> 8;
        int rem = gcp & 255;
        uint4 v4 = *(uint4*)&sbuf[row * 100 + q4 * 4];
        size_t rb = ((size_t)((s * 3 + which) * 8 + b)) * 4096;
        *(uint4*)&g_qkv_h[(rb + n0 + row) * 256 + rem] = v4;
    }
}

// ---------------------------------------------------------------------------
// Kernel 2a: Gram partials via ldmatrix.trans. grid (chunk 8, bh 64, s 2)
// ---------------------------------------------------------------------------
__global__ __launch_bounds__(256) void attn_gram_kernel()
{
    extern __shared__ char dsm[];
    uint32_t sbr = smem_u32(dsm);
    uint32_t sb = (sbr + 1023) & ~1023u;

    const int tid = threadIdx.x;
    const int wid = tid >> 5;
    const int lane = tid & 31;
    const int wm = wid & 1, wn = wid >> 1;
    const int chunk = blockIdx.x;
    const int bh = blockIdx.y;
    const int s = blockIdx.z;
    const int b = bh >> 3, h = bh & 7;
    const int so = s ^ 1;
    const int g = s * 64 + bh;

    const size_t qb = ((size_t)((s  * 3 + 0) * 8 + b)) * 4096;
    const size_t kb = ((size_t)((so * 3 + 1) * 8 + b)) * 4096;

    float acc[2][2][4];
#pragma unroll
    for (int i = 0; i < 2; i++)
#pragma unroll
        for (int j = 0; j < 2; j++)
#pragma unroll
            for (int r = 0; r < 4; r++) acc[i][j][r] = 0.f;

    auto fill_sub = [&](int st, int sub) {
        int tok0 = chunk * 512 + sub * 64;
#pragma unroll
        for (int it = 0; it < 2; it++) {
            int idx = tid + it * 256;
            int r = idx >> 3, c16 = idx & 7;
            uint32_t dsw = swz((uint32_t)(r * 128 + c16 * 16));
            CP_ASYNC16(sb + SG_Q(st) + dsw, g_qkv_h + (qb + tok0 + r) * 256 + h * 32 + c16 * 4);
            CP_ASYNC16(sb + SG_K(st) + dsw, g_qkv_h + (kb + tok0 + r) * 256 + h * 32 + c16 * 4);
        }
        CP_COMMIT();
    };

    const int aTrowOff = ((lane >> 4) & 1) * 8 + (lane & 7);
    const int aDcolOff = ((lane >> 3) & 1) * 8;
    const int bTrowOff = ((lane >> 3) & 1) * 8 + (lane & 7);
    const int bEcolOff = ((lane >> 4) & 1) * 8;

    fill_sub(0, 0);
    for (int sub = 0; sub < 8; sub++) {
        int st = sub & 1;
        if (sub < 7) fill_sub(st ^ 1, sub + 1);
        if (sub < 7) CP_WAIT1(); else CP_WAIT0();
        __syncthreads();
#pragma unroll
        for (int kk = 0; kk < 4; kk++) {
            const int t0 = kk * 16;
            uint32_t qh[2][4], kf[2][2];
#pragma unroll
            for (int mt = 0; mt < 2; mt++) {
                int d0 = wm * 32 + mt * 16;
                ldmx4t(qh[mt][0], qh[mt][1], qh[mt][2], qh[mt][3],
                       sb + SG_Q(st) + swz((uint32_t)((t0 + aTrowOff) * 128 + (d0 + aDcolOff) * 2)));
            }
            {
                int e0 = wn * 16;
                ldmx4t(kf[0][0], kf[0][1], kf[1][0], kf[1][1],
                       sb + SG_K(st) + swz((uint32_t)((t0 + bTrowOff) * 128 + (e0 + bEcolOff) * 2)));
            }
#pragma unroll
            for (int mt = 0; mt < 2; mt++)
#pragma unroll
                for (int nt = 0; nt < 2; nt++)
                    mma_h(acc[mt][nt], qh[mt], kf[nt]);
        }
        __syncthreads();
    }

    const size_t base = (size_t)(g * 8 + chunk) * 4096;
#pragma unroll
    for (int mt = 0; mt < 2; mt++)
#pragma unroll
        for (int nt = 0; nt < 2; nt++) {
            int m = wm * 32 + mt * 16 + (lane >> 2);
            int col = wn * 16 + nt * 8 + 2 * (lane & 3);
            *(float2*)&g_pgram[base + m * 64 + col] = make_float2(acc[mt][nt][0], acc[mt][nt][1]);
            *(float2*)&g_pgram[base + (m + 8) * 64 + col] = make_float2(acc[mt][nt][2], acc[mt][nt][3]);
        }
}

// ---------------------------------------------------------------------------
// Kernel 2b: softmax split over d halves. grid (g 128, half 2), 256 threads.
// ---------------------------------------------------------------------------
__global__ __launch_bounds__(256) void attn_softmax_kernel(
    const float* __restrict__ temp_rgb, const float* __restrict__ temp_T)
{
    const int g = blockIdx.x;
    const int p = blockIdx.y;           // d half: rows p*32 .. p*32+31
    const int s = g >> 6;
    const int bh = g & 63;
    const int b = bh >> 3, h = bh & 7;
    const int so = s ^ 1;
    const float temp = (s ? temp_T : temp_rgb)[h];

    __shared__ float qinv[32], kinv[64];
    const int tid = threadIdx.x;

    if (tid < 32) {
        float sq = 0.f;
        size_t nb = (((size_t)(s * 2 + 0) * 8 + b) * 512 + h * 64 + p * 32 + tid) * 64;
#pragma unroll
        for (int t = 0; t < 64; t++) sq += g_nrm[nb + t];
        qinv[tid] = 1.f / fmaxf(sqrtf(sq), 1e-12f);
    } else if (tid >= 64 && tid < 128) {
        float sk = 0.f;
        size_t nb = (((size_t)(so * 2 + 1) * 8 + b) * 512 + h * 64 + tid - 64) * 64;
#pragma unroll
        for (int t = 0; t < 64; t++) sk += g_nrm[nb + t];
        kinv[tid - 64] = 1.f / fmaxf(sqrtf(sk), 1e-12f);
    }
    __syncthreads();

    const int wid = tid >> 5, lane = tid & 31;
    const int j0 = lane * 2;
    const float ki0 = kinv[j0], ki1 = kinv[j0 + 1];
#pragma unroll
    for (int r = 0; r < 4; r++) {
        int dl = wid * 4 + r;            // 0..31
        int d = p * 32 + dl;
        float v0 = 0.f, v1 = 0.f;
#pragma unroll
        for (int c = 0; c < 8; c++) {
            float2 pv = *(const float2*)&g_pgram[(size_t)(g * 8 + c) * 4096 + d * 64 + j0];
            v0 += pv.x; v1 += pv.y;
        }
        float sc = temp * qinv[dl];
        v0 *= sc * ki0;
        v1 *= sc * ki1;
        float mx = fmaxf(v0, v1);
#pragma unroll
        for (int o = 16; o; o >>= 1) mx = fmaxf(mx, __shfl_xor_sync(0xFFFFFFFFu, mx, o));
        float e0 = __expf(v0 - mx), e1 = __expf(v1 - mx);
        float sm = e0 + e1;
#pragma unroll
        for (int o = 16; o; o >>= 1) sm += __shfl_xor_sync(0xFFFFFFFFu, sm, o);
        float inv = 1.f / sm;
        g_p_h[(size_t)g * 2048 + d * 32 + lane] = cvt1h(e0 * inv, e1 * inv);
    }
}

// ---------------------------------------------------------------------------
// Kernel 2c: out = P @ v, 2 n-tiles per CTA. grid (tile 16, bh 64, s 2)
// ---------------------------------------------------------------------------
__global__ __launch_bounds__(256) void attn_pv_kernel()
{
    extern __shared__ char dsm[];
    uint32_t sbr = smem_u32(dsm);
    uint32_t sb = (sbr + 1023) & ~1023u;

    const int tid = threadIdx.x;
    const int wid = tid >> 5;
    const int lane = tid & 31;
    const int wm = wid & 1, wn = wid >> 1;
    const int n0 = blockIdx.x * 256;
    const int bh = blockIdx.y;
    const int s = blockIdx.z;
    const int b = bh >> 3, h = bh & 7;
    const int so = s ^ 1;
    const int g = s * 64 + bh;
    const size_t vb = ((size_t)((so * 3 + 2) * 8 + b)) * 4096;

    // group 0: P + V tile0 ; group 1: V tile1
#pragma unroll
    for (int it = 0; it < 2; it++) {
        int idx = tid + it * 256;
        int r = idx >> 3, c16 = idx & 7;
        uint32_t dsw = swz((uint32_t)(r * 128 + c16 * 16));
        CP_ASYNC16(sb + SP_P + dsw, g_p_h + (size_t)g * 2048 + r * 32 + c16 * 4);
    }
#pragma unroll
    for (int it = 0; it < 4; it++) {
        int idx = tid + it * 256;
        int r = idx >> 3, c16 = idx & 7;
        uint32_t dsw = swz((uint32_t)(r * 128 + c16 * 16));
        CP_ASYNC16(sb + SP_V(0) + dsw, g_qkv_h + (vb + n0 + r) * 256 + h * 32 + c16 * 4);
    }
    CP_COMMIT();
#pragma unroll
    for (int it = 0; it < 4; it++) {
        int idx = tid + it * 256;
        int r = idx >> 3, c16 = idx & 7;
        uint32_t dsw = swz((uint32_t)(r * 128 + c16 * 16));
        CP_ASYNC16(sb + SP_V(1) + dsw, g_qkv_h + (vb + n0 + 128 + r) * 256 + h * 32 + c16 * 4);
    }
    CP_COMMIT();

    const int aRow  = wm * 64 + (lane & 15);
    const int aColb = (lane >> 4) * 16;
    const int bRow  = wn * 16 + (lane & 7) + ((lane >> 4) & 1) * 8;
    const int bColb = ((lane >> 3) & 1) * 16;
    const size_t ob = (size_t)(s * 8 + b) * 4096;

#pragma unroll
    for (int t = 0; t < 2; t++) {
        if (t == 0) CP_WAIT1(); else CP_WAIT0();
        __syncthreads();

        float acc[4][2][4];
#pragma unroll
        for (int i = 0; i < 4; i++)
#pragma unroll
            for (int j = 0; j < 2; j++)
#pragma unroll
                for (int r = 0; r < 4; r++) acc[i][j][r] = 0.f;

#pragma unroll
        for (int kk = 0; kk < 4; kk++) {
            uint32_t vh[4][4], pf[2][2];
#pragma unroll
            for (int mt = 0; mt < 4; mt++)
                ldmx4(vh[mt][0], vh[mt][1], vh[mt][2], vh[mt][3],
                      sb + SP_V(t) + swz((uint32_t)((aRow + mt * 16) * 128 + aColb + kk * 32)));
            ldmx4(pf[0][0], pf[0][1], pf[1][0], pf[1][1],
                  sb + SP_P + swz((uint32_t)(bRow * 128 + bColb + kk * 32)));
#pragma unroll
            for (int mt = 0; mt < 4; mt++)
#pragma unroll
                for (int nt = 0; nt < 2; nt++)
                    mma_h(acc[mt][nt], vh[mt], pf[nt]);
        }

#pragma unroll
        for (int mt = 0; mt < 4; mt++) {
            int tok = n0 + t * 128 + wm * 64 + mt * 16 + (lane >> 2);
#pragma unroll
            for (int nt = 0; nt < 2; nt++) {
                int dp = wn * 8 + nt * 4 + (lane & 3);
                size_t a0 = (ob + tok) * 256 + h * 32 + dp;
                g_att_h[a0]           = cvt1h(acc[mt][nt][0], acc[mt][nt][1]);
                g_att_h[a0 + 8 * 256] = cvt1h(acc[mt][nt][2], acc[mt][nt][3]);
            }
        }
    }
}

// ---------------------------------------------------------------------------
// Kernel 3: proj GEMM. grid (cTile 4, nTile 32, sb 16), 128 threads, 2 CTA/SM.
// ---------------------------------------------------------------------------
__device__ __forceinline__ void fill_proj(uint32_t sb, int st, int tid, int kp0,
    size_t aBase, size_t bBase)
{
#pragma unroll
    for (int it = 0; it < 8; it++) {
        int idx = tid + it * 128;
        int r = idx >> 3, c16 = idx & 7;
        uint32_t dsw = swz((uint32_t)(r * 128 + c16 * 16));
        CP_ASYNC16(sb + SQ_A(st) + dsw, g_att_h + aBase + (size_t)r * 256 + kp0 + c16 * 4);
    }
#pragma unroll
    for (int it = 0; it < 8; it++) {
        int idx = tid + it * 128;
        int r = idx >> 3, c16 = idx & 7;
        uint32_t dsw = swz((uint32_t)(r * 128 + c16 * 16));
        CP_ASYNC16(sb + SQ_B(st) + dsw, g_wp_h + bBase + (size_t)r * 256 + kp0 + c16 * 4);
    }
    CP_COMMIT();
}

__global__ __launch_bounds__(128, 2) void proj_mma_kernel(
    const float* __restrict__ br, const float* __restrict__ bt,
    float* __restrict__ out)
{
    extern __shared__ char dsm[];
    uint32_t sbr = smem_u32(dsm);
    uint32_t sb = (sbr + 1023) & ~1023u;
    char* ab = dsm + (sb - sbr);

    const int tid = threadIdx.x;
    const int wid = tid >> 5;
    const int lane = tid & 31;
    const int wm = wid & 1, wn = wid >> 1;
    const int z = blockIdx.z;
    const int s = z >> 3, b = z & 7;
    const float* __restrict__ bias = s ? bt : br;
    const int n0 = blockIdx.y * 128;
    const int c0 = blockIdx.x * 128;

    const size_t aBase = (((size_t)(s * 8 + b)) * 4096 + n0) * 256;
    const size_t bBase = ((size_t)s * 512 + c0) * 256;

    float acc[4][8][4];
#pragma unroll
    for (int i = 0; i < 4; i++)
#pragma unroll
        for (int j = 0; j < 8; j++)
#pragma unroll
            for (int r = 0; r < 4; r++) acc[i][j][r] = 0.f;

    const int aRow  = wm * 64 + (lane & 15);
    const int aColb = (lane >> 4) * 16;
    const int bRow  = wn * 64 + (lane & 7) + ((lane >> 4) & 1) * 8;
    const int bColb = ((lane >> 3) & 1) * 16;

    fill_proj(sb, 0, tid, 0, aBase, bBase);
    for (int c = 0; c < 8; c++) {
        int st = c & 1;
        if (c < 7) fill_proj(sb, st ^ 1, tid, (c + 1) * 32, aBase, bBase);
        if (c < 7) CP_WAIT1(); else CP_WAIT0();
        __syncthreads();
#pragma unroll
        for (int kk = 0; kk < 4; kk++) {
            uint32_t ah[4][4], bf[8][2];
#pragma unroll
            for (int mt = 0; mt < 4; mt++)
                ldmx4(ah[mt][0], ah[mt][1], ah[mt][2], ah[mt][3],
                      sb + SQ_A(st) + swz((uint32_t)((aRow + mt * 16) * 128 + aColb + kk * 32)));
#pragma unroll
            for (int j = 0; j < 4; j++)
                ldmx4(bf[2 * j][0], bf[2 * j][1], bf[2 * j + 1][0], bf[2 * j + 1][1],
                      sb + SQ_B(st) + swz((uint32_t)((bRow + j * 16) * 128 + bColb + kk * 32)));
#pragma unroll
            for (int mt = 0; mt < 4; mt++)
#pragma unroll
                for (int nj = 0; nj < 8; nj++)
                    mma_h(acc[mt][nj], ah[mt], bf[nj]);
        }
        __syncthreads();
    }

    // epilogue: [token][channel] + bias via smem transpose (2 passes over wm)
    float* sT = (float*)ab;   // 64 x 132 fp32
    float* outp = out + (size_t)(s * 8 + b) * 2097152;
#pragma unroll
    for (int p = 0; p < 2; p++) {
        if (wm == p) {
#pragma unroll
            for (int mt = 0; mt < 4; mt++)
#pragma unroll
                for (int nj = 0; nj < 8; nj++) {
                    int m = mt * 16 + (lane >> 2);
                    int cc = wn * 64 + nj * 8 + 2 * (lane & 3);
                    sT[m * 132 + cc]           = acc[mt][nj][0];
                    sT[m * 132 + cc + 1]       = acc[mt][nj][1];
                    sT[(m + 8) * 132 + cc]     = acc[mt][nj][2];
                    sT[(m + 8) * 132 + cc + 1] = acc[mt][nj][3];
                }
        }
        __syncthreads();
#pragma unroll
        for (int it = 0; it < 16; it++) {
            int idx = tid + it * 128;
            int row = idx >> 5, ch4 = (idx & 31) * 4;
            int tok = n0 + p * 64 + row;
            float4 vv = *(float4*)&sT[row * 132 + ch4];
            float4 bb = *(const float4*)&bias[c0 + ch4];
            vv.x += bb.x; vv.y += bb.y; vv.z += bb.z; vv.w += bb.w;
            *(float4*)&outp[(size_t)tok * 512 + c0 + ch4] = vv;
        }
        __syncthreads();
    }
}

// ---------------------------------------------------------------------------
extern "C" void kernel_launch(void* const* d_in, const int* in_sizes, int n_in,
                              void* d_out, int out_size)
{
    const float* x        = (const float*)d_in[0];
    const float* x_d      = (const float*)d_in[1];
    const float* W_qkv_r  = (const float*)d_in[2];
    const float* W_qkv_T  = (const float*)d_in[3];
    const float* temp_r   = (const float*)d_in[4];
    const float* temp_T   = (const float*)d_in[5];
    const float* W_proj_r = (const float*)d_in[6];
    const float* b_proj_r = (const float*)d_in[7];
    const float* W_proj_T = (const float*)d_in[8];
    const float* b_proj_T = (const float*)d_in[9];
    float* out = (float*)d_out;

    cudaFuncSetAttribute(qkv_mma_kernel,
        cudaFuncAttributeMaxDynamicSharedMemorySize, QKV_SMEM);
    cudaFuncSetAttribute(proj_mma_kernel,
        cudaFuncAttributeMaxDynamicSharedMemorySize, PROJ_SMEM);
    cudaFuncSetAttribute(attn_gram_kernel,
        cudaFuncAttributeMaxDynamicSharedMemorySize, GRAM_SMEM);
    cudaFuncSetAttribute(attn_pv_kernel,
        cudaFuncAttributeMaxDynamicSharedMemorySize, PV_SMEM);

    prep_kernel<<<(PREP_X_THREADS + 2 * 1536 * 256 + 2 * 512 * 256 + 255) / 256, 256>>>(
        x, x_d, W_qkv_r, W_qkv_T, W_proj_r, W_proj_T);

    {
        dim3 grid(8, 256, 2);     // c-tile fastest -> X slice L2-reused
        qkv_mma_kernel<<<grid, 128, QKV_SMEM>>>();
    }
    {
        dim3 g1(8, 64, 2);
        attn_gram_kernel<<<g1, 256, GRAM_SMEM>>>();
        dim3 gs(128, 2);
        attn_softmax_kernel<<<gs, 256>>>(temp_r, temp_T);
        dim3 g2(16, 64, 2);
        attn_pv_kernel<<<g2, 256, PV_SMEM>>>();
    }
    {
        dim3 grid(4, 32, 16);     // c-tile fastest
        proj_mma_kernel<<<grid, 128, PROJ_SMEM>>>(b_proj_r, b_proj_T, out);
    }
}